// round 15
// baseline (speedup 1.0000x reference)
#include <cuda_runtime.h>
#include <cstdint>

#define N_NODES 50000
#define N_EDGES 1600000
#define ND 64
#define HD 128
#define ED 32
#define MI 160
#define TILE_E 16
#define NTILES (N_EDGES / TILE_E)    // 100000
#define THREADS 512
#define FULLMASK 0xffffffffu

#define KT1 20
#define NT1 32
#define KT2 16
#define W1F_WORDS (KT1 * NT1 * 64)   // 40960
#define W2F_WORDS (KT2 * 8 * 64)     // 8192
#define MI_STRIDE 164
#define HID_STRIDE 132
#define MI_QWORDS (TILE_E * MI_STRIDE)  // 2624

// smem word offsets
#define OFF_W1F   0
#define OFF_MI    40960              // 4 quarters x 2624 = 10496
#define OFF_EW2   51456
#define OFF_B1    52480
#define OFF_B2    52736
#define OFF_CW2   52800
#define OFF_EW1   52928
#define OFF_EB1   52960
#define OFF_EB2   52992
#define OFF_CPART 53024              // 4 x 32
#define OFF_SRC   53152              // 4 x 16
#define OFF_DST   53216              // 4 x 16
#define SMEM_WORDS 53280             // 213,120 bytes

typedef unsigned int u32;

__device__ int g_is64;
__device__ int g_src[N_EDGES];
__device__ int g_dst[N_EDGES];
__device__ u32 g_w1f[W1F_WORDS];
__device__ u32 g_w2f[W2F_WORDS];

__global__ void detect_kernel(const unsigned int* __restrict__ w) {
    if (blockIdx.x == 0 && threadIdx.x == 0) {
        int is64 = 1;
        for (int i = 0; i < 64; i++)
            if (w[2 * i + 1] != 0u) { is64 = 0; break; }
        g_is64 = is64;
    }
}

__global__ void convert_kernel(const void* __restrict__ p) {
    int i = blockIdx.x * blockDim.x + threadIdx.x;
    if (i >= N_EDGES) return;
    if (g_is64) {
        const long long* q = (const long long*)p;
        g_src[i] = (int)q[i];
        g_dst[i] = (int)q[N_EDGES + i];
    } else {
        const int* q = (const int*)p;
        g_src[i] = q[i];
        g_dst[i] = q[N_EDGES + i];
    }
}

__global__ void init_out_kernel(const float* __restrict__ h,
                                const float* __restrict__ x,
                                float* __restrict__ out) {
    int i = blockIdx.x * blockDim.x + threadIdx.x;
    const int nh = N_NODES * ND;
    const int total = nh + N_NODES * 3;
    if (i < nh) out[i] = h[i];
    else if (i < total) out[i] = x[i - nh];
}

__device__ __forceinline__ u32 tf32b(float f) {
    u32 u;
    asm("cvt.rna.tf32.f32 %0, %1;" : "=r"(u) : "f"(f));
    return u;
}
// silu(v) = hv + hv*tanh(hv), hv = v/2 : 1 MUFU
__device__ __forceinline__ float silu(float v) {
    float hv = 0.5f * v, t;
    asm("tanh.approx.f32 %0, %1;" : "=f"(t) : "f"(hv));
    return fmaf(hv, t, hv);
}
__device__ __forceinline__ void mma_tf32(
    float& d0, float& d1, float& d2, float& d3,
    u32 a0, u32 a1, u32 a2, u32 a3, u32 b0, u32 b1) {
    asm volatile(
        "mma.sync.aligned.m16n8k8.row.col.f32.tf32.tf32.f32 "
        "{%0,%1,%2,%3}, {%4,%5,%6,%7}, {%8,%9}, {%0,%1,%2,%3};"
        : "+f"(d0), "+f"(d1), "+f"(d2), "+f"(d3)
        : "r"(a0), "r"(a1), "r"(a2), "r"(a3), "r"(b0), "r"(b1));
}
__device__ __forceinline__ void ldsm4(u32& r0, u32& r1, u32& r2, u32& r3, u32 addr) {
    asm volatile("ldmatrix.sync.aligned.m8n8.x4.shared.b16 {%0,%1,%2,%3}, [%4];"
                 : "=r"(r0), "=r"(r1), "=r"(r2), "=r"(r3) : "r"(addr));
}
__device__ __forceinline__ u32 smem_u32(const void* p) {
    return (u32)__cvta_generic_to_shared(p);
}

// Fragment layouts (nt-pair quads) — unchanged from R12/R13.
__global__ void build_frags(const float* __restrict__ nw1,
                            const float* __restrict__ cw1,
                            const float* __restrict__ nw2) {
    int i = blockIdx.x * blockDim.x + threadIdx.x;
    if (i < W1F_WORDS) {
        int w = i & 3, lane = (i >> 2) & 31, ntp = (i >> 7) & 15, kt = i >> 11;
        int nt = 2 * ntp + (w >> 1), word = w & 1;
        int n = nt * 8 + (lane >> 2);
        int k = kt * 8 + (lane & 3) + 4 * word;
        float v = (n < HD) ? nw1[k * HD + n] : cw1[k * HD + (n - HD)];
        g_w1f[i] = tf32b(v);
    }
    if (i < W2F_WORDS) {
        int w = i & 3, lane = (i >> 2) & 31, ntp = (i >> 7) & 3, kt = i >> 9;
        int nt = 2 * ntp + (w >> 1), word = w & 1;
        int n = nt * 8 + (lane >> 2);
        int k = kt * 8 + (lane & 3) + 4 * word;
        g_w2f[i] = tf32b(nw2[k * ND + n]);
    }
}

// ---------------------------------------------------------------------------
// 512 threads = FOUR independent 4-warp quarter-pipelines (16-edge tiles)
// sharing weight smem; per-quarter named barriers maximize cross-stream
// overlap (4 barrier-independent warps per SMSP).
// ---------------------------------------------------------------------------
__global__ void __launch_bounds__(THREADS, 1)
egnn_mma_kernel(const float* __restrict__ h, const float* __restrict__ x,
                const float* __restrict__ edge_dist,
                const float* __restrict__ node_b1, const float* __restrict__ node_b2,
                const float* __restrict__ coord_b1, const float* __restrict__ coord_w2,
                const float* __restrict__ edge_w1, const float* __restrict__ edge_b1,
                const float* __restrict__ edge_w2, const float* __restrict__ edge_b2,
                float* __restrict__ out) {
    extern __shared__ u32 sm[];
    u32* s_w1f = sm + OFF_W1F;
    float* s_ew2f = (float*)(sm + OFF_EW2);
    float* s_b1f  = (float*)(sm + OFF_B1);
    float* s_b2f  = (float*)(sm + OFF_B2);
    float* s_cw2f = (float*)(sm + OFF_CW2);
    float* s_ew1f = (float*)(sm + OFF_EW1);
    float* s_eb1f = (float*)(sm + OFF_EB1);
    float* s_eb2f = (float*)(sm + OFF_EB2);

    const int tid = threadIdx.x;
    const int lane = tid & 31;
    const int warp = tid >> 5;        // 0..15
    const int quarter = warp >> 2;    // 0..3
    const int qw = warp & 3;          // warp-in-quarter
    const int qtid = tid & 127;

    u32* s_mi = sm + OFF_MI + quarter * MI_QWORDS;
    float* s_cpart = (float*)(sm + OFF_CPART) + quarter * 32;
    int* s_srci = (int*)(sm + OFF_SRC) + quarter * TILE_E;
    int* s_dsti = (int*)(sm + OFF_DST) + quarter * TILE_E;

    {
        const uint4* src1 = (const uint4*)g_w1f;
        uint4* dst1 = (uint4*)s_w1f;
        for (int i = tid; i < W1F_WORDS / 4; i += THREADS) dst1[i] = src1[i];
    }
    for (int i = tid; i < ED * ED; i += THREADS) s_ew2f[i] = edge_w2[i];
    if (tid < 256) s_b1f[tid] = (tid < HD) ? node_b1[tid] : coord_b1[tid - HD];
    if (tid < ND) s_b2f[tid] = node_b2[tid];
    if (tid < HD) s_cw2f[tid] = coord_w2[tid];
    if (tid < ED) {
        s_ew1f[tid] = edge_w1[tid];
        s_eb1f[tid] = edge_b1[tid];
        s_eb2f[tid] = edge_b2[tid];
    }
    __syncthreads();

    float* out_h = out;
    float* out_x = out + (size_t)N_NODES * ND;

    const int r = lane >> 2;
    const int c = lane & 3;
    const int ge = qtid >> 3;     // edge 0..15
    const int gp = qtid & 7;      // 16B chunk 0..7
    const int barid = quarter + 1;

    const u32 lmrow = (lane & 15);
    const u32 lmcol = (lane >> 4) * 4;
    const u32 lm_a_base = smem_u32(s_mi) + ((lmrow * MI_STRIDE + lmcol) << 2);
    const u32 lm_h_base = smem_u32(s_mi) + ((lmrow * HID_STRIDE + lmcol) << 2);

#define QBAR() asm volatile("bar.sync %0, 128;" :: "r"(barid) : "memory")

    const int tstride = gridDim.x * 4;
    const int t0 = blockIdx.x * 4 + quarter;

    // cross-iteration register prefetch: indices + dists for the NEXT tile
    int nse = 0, nde = 0;
    float ndist[4] = {0, 0, 0, 0};
    if (t0 < NTILES) {
        nse = g_src[t0 * TILE_E + ge];
        nde = g_dst[t0 * TILE_E + ge];
#pragma unroll
        for (int q = 0; q < 4; q++) ndist[q] = edge_dist[t0 * TILE_E + qw * 4 + q];
    }

    for (int tile = t0; tile < NTILES; tile += tstride) {
        const int se = nse, de = nde;
        float dcur[4];
#pragma unroll
        for (int q = 0; q < 4; q++) dcur[q] = ndist[q];

        // ---- gather h rows (tf32 inline) + indices
        {
            if (gp == 0) { s_srci[ge] = se; s_dsti[ge] = de; }
            const uint4* hs = (const uint4*)(h + (size_t)se * ND);
            const uint4* hd = (const uint4*)(h + (size_t)de * ND);
            uint4 v0 = hs[gp], v1 = hs[gp + 8], v2 = hd[gp], v3 = hd[gp + 8];
            uint4* mrow = (uint4*)(s_mi + ge * MI_STRIDE);
            mrow[gp] = make_uint4(tf32b(__uint_as_float(v0.x)), tf32b(__uint_as_float(v0.y)),
                                  tf32b(__uint_as_float(v0.z)), tf32b(__uint_as_float(v0.w)));
            mrow[gp + 8] = make_uint4(tf32b(__uint_as_float(v1.x)), tf32b(__uint_as_float(v1.y)),
                                      tf32b(__uint_as_float(v1.z)), tf32b(__uint_as_float(v1.w)));
            mrow[gp + 16] = make_uint4(tf32b(__uint_as_float(v2.x)), tf32b(__uint_as_float(v2.y)),
                                       tf32b(__uint_as_float(v2.z)), tf32b(__uint_as_float(v2.w)));
            mrow[gp + 24] = make_uint4(tf32b(__uint_as_float(v3.x)), tf32b(__uint_as_float(v3.y)),
                                       tf32b(__uint_as_float(v3.z)), tf32b(__uint_as_float(v3.w)));
        }
        // ---- edge MLP (4 edges per warp)
#pragma unroll
        for (int q = 0; q < 4; q++) {
            const int e = qw * 4 + q;
            float t0v = silu(fmaf(dcur[q], s_ew1f[lane], s_eb1f[lane]));
            float acc0 = s_eb2f[lane];
#pragma unroll 8
            for (int k = 0; k < ED; k++) {
                float tv = __shfl_sync(FULLMASK, t0v, k);
                acc0 = fmaf(tv, s_ew2f[k * ED + lane], acc0);
            }
            s_mi[e * MI_STRIDE + 2 * ND + lane] = tf32b(acc0);
        }
        // ---- issue next tile's index/dist loads (retire under MMA1)
        {
            const int ntile = tile + tstride;
            if (ntile < NTILES) {
                nse = g_src[ntile * TILE_E + ge];
                nde = g_dst[ntile * TILE_E + ge];
#pragma unroll
                for (int q = 0; q < 4; q++)
                    ndist[q] = edge_dist[ntile * TILE_E + qw * 4 + q];
            }
        }
        QBAR();

        // ---- qw3: x coords prefetch (overlaps MMA1)
        float xs0 = 0, xs1 = 0, xs2 = 0, xd0 = 0, xd1 = 0, xd2 = 0;
        if (qw == 3 && lane < TILE_E) {
            const float* xs = x + (size_t)s_srci[lane] * 3;
            const float* xd = x + (size_t)s_dsti[lane] * 3;
            xs0 = xs[0]; xs1 = xs[1]; xs2 = xs[2];
            xd0 = xd[0]; xd1 = xd[1]; xd2 = xd[2];
        }

        // ---- MMA1: [16,160] x [160,256]; warp qw -> cols 64qw..64qw+63
        float acc[8][4];
#pragma unroll
        for (int nt = 0; nt < 8; nt++)
#pragma unroll
            for (int q = 0; q < 4; q++) acc[nt][q] = 0.0f;

#pragma unroll 4
        for (int kt = 0; kt < KT1; kt++) {
            u32 a0, a1, a2, a3;
            ldsm4(a0, a1, a2, a3, lm_a_base + (kt * 8 << 2));
#pragma unroll
            for (int p = 0; p < 4; p++) {
                uint4 bv = *(const uint4*)&s_w1f[((kt * 16 + qw * 4 + p) * 32 + lane) * 4];
                mma_tf32(acc[2 * p][0], acc[2 * p][1], acc[2 * p][2], acc[2 * p][3],
                         a0, a1, a2, a3, bv.x, bv.y);
                mma_tf32(acc[2 * p + 1][0], acc[2 * p + 1][1],
                         acc[2 * p + 1][2], acc[2 * p + 1][3],
                         a0, a1, a2, a3, bv.z, bv.w);
            }
        }

        // ---- coord warps (qw 2,3): silu + weighted reduce -> cpart
        if (qw >= 2) {
            const int cw0 = (qw - 2) * 64;
            float pr = 0.0f, pr8 = 0.0f;
#pragma unroll
            for (int nt = 0; nt < 8; nt++) {
                const int cc = cw0 + nt * 8 + 2 * c;
                float b1a = s_b1f[HD + cc], b1b = s_b1f[HD + cc + 1];
                float w2a = s_cw2f[cc], w2b = s_cw2f[cc + 1];
                pr  = fmaf(silu(acc[nt][0] + b1a), w2a, pr);
                pr  = fmaf(silu(acc[nt][1] + b1b), w2b, pr);
                pr8 = fmaf(silu(acc[nt][2] + b1a), w2a, pr8);
                pr8 = fmaf(silu(acc[nt][3] + b1b), w2b, pr8);
            }
            pr  += __shfl_xor_sync(FULLMASK, pr, 1);
            pr  += __shfl_xor_sync(FULLMASK, pr, 2);
            pr8 += __shfl_xor_sync(FULLMASK, pr8, 1);
            pr8 += __shfl_xor_sync(FULLMASK, pr8, 2);
            if (c == 0) {
                s_cpart[(qw - 2) * 16 + r] = pr;
                s_cpart[(qw - 2) * 16 + r + 8] = pr8;
            }
        }
        QBAR();   // A-frag reads done; cpart visible

        // ---- node warps (qw 0,1): silu'd hidden -> s_mi; qw3: x scatter
        if (qw < 2) {
#pragma unroll
            for (int nt = 0; nt < 8; nt++) {
                const int col = qw * 64 + nt * 8 + 2 * c;
                float b1a = s_b1f[col], b1b = s_b1f[col + 1];
                u32 v0 = tf32b(silu(acc[nt][0] + b1a));
                u32 v1 = tf32b(silu(acc[nt][1] + b1b));
                u32 v2 = tf32b(silu(acc[nt][2] + b1a));
                u32 v3 = tf32b(silu(acc[nt][3] + b1b));
                u32* row0 = s_mi + r * HID_STRIDE + col;
                u32* row8 = row0 + 8 * HID_STRIDE;
                *(uint2*)row0 = make_uint2(v0, v1);
                *(uint2*)row8 = make_uint2(v2, v3);
            }
        } else if (qw == 3 && lane < TILE_E) {
            float cwv = s_cpart[lane] + s_cpart[16 + lane];
            float dx = xs0 - xd0, dy = xs1 - xd1, dz = xs2 - xd2;
            float len = fmaxf(sqrtf(dx * dx + dy * dy + dz * dz), 1e-8f);
            float s = __fdividef(cwv, len);
            float* dstx = out_x + (size_t)s_dsti[lane] * 3;
            atomicAdd(dstx + 0, s * dx);
            atomicAdd(dstx + 1, s * dy);
            atomicAdd(dstx + 2, s * dz);
        }
        QBAR();   // hidden ready

        // ---- MMA2: [16,128] x [128,64]; warp qw -> cols 16qw..16qw+15
        {
            float a2[2][4];
#pragma unroll
            for (int nt = 0; nt < 2; nt++)
#pragma unroll
                for (int q = 0; q < 4; q++) a2[nt][q] = 0.0f;

#pragma unroll 4
            for (int kt = 0; kt < KT2; kt++) {
                u32 a0, a1, av2, a3;
                ldsm4(a0, a1, av2, a3, lm_h_base + (kt * 8 << 2));
                uint4 bv = __ldg((const uint4*)g_w2f + (kt * 4 + qw) * 32 + lane);
                mma_tf32(a2[0][0], a2[0][1], a2[0][2], a2[0][3],
                         a0, a1, av2, a3, bv.x, bv.y);
                mma_tf32(a2[1][0], a2[1][1], a2[1][2], a2[1][3],
                         a0, a1, av2, a3, bv.z, bv.w);
            }
#pragma unroll
            for (int nt = 0; nt < 2; nt++) {
                const int col = qw * 16 + nt * 8 + 2 * c;
                float b2a = s_b2f[col], b2b = s_b2f[col + 1];
                float* baseA = out_h + (size_t)s_dsti[r] * ND + col;
                atomicAdd((float2*)baseA, make_float2(a2[nt][0] + b2a, a2[nt][1] + b2b));
                float* baseB = out_h + (size_t)s_dsti[r + 8] * ND + col;
                atomicAdd((float2*)baseB, make_float2(a2[nt][2] + b2a, a2[nt][3] + b2b));
            }
        }
        QBAR();   // MI/index reads complete before next gather overwrites
    }
#undef QBAR
}

extern "C" void kernel_launch(void* const* d_in, const int* in_sizes, int n_in,
                              void* d_out, int out_size) {
    const float* h        = (const float*)d_in[0];
    const float* x        = (const float*)d_in[1];
    const void*  eidx     = d_in[2];
    const float* edist    = (const float*)d_in[3];
    const float* node_w1  = (const float*)d_in[4];
    const float* node_b1  = (const float*)d_in[5];
    const float* node_w2  = (const float*)d_in[6];
    const float* node_b2  = (const float*)d_in[7];
    const float* coord_w1 = (const float*)d_in[8];
    const float* coord_b1 = (const float*)d_in[9];
    const float* coord_w2 = (const float*)d_in[10];
    const float* edge_w1  = (const float*)d_in[11];
    const float* edge_b1  = (const float*)d_in[12];
    const float* edge_w2  = (const float*)d_in[13];
    const float* edge_b2  = (const float*)d_in[14];
    float* out = (float*)d_out;

    (void)in_sizes; (void)n_in; (void)out_size;

    detect_kernel<<<1, 32>>>((const unsigned int*)eidx);
    convert_kernel<<<(N_EDGES + 255) / 256, 256>>>(eidx);
    build_frags<<<(W1F_WORDS + 255) / 256, 256>>>(node_w1, coord_w1, node_w2);

    const int total_out = N_NODES * ND + N_NODES * 3;
    init_out_kernel<<<(total_out + 255) / 256, 256>>>(h, x, out);

    const int smem_bytes = SMEM_WORDS * 4;
    cudaFuncSetAttribute(egnn_mma_kernel,
                         cudaFuncAttributeMaxDynamicSharedMemorySize, smem_bytes);

    int nsm = 148;
    cudaDeviceGetAttribute(&nsm, cudaDevAttrMultiProcessorCount, 0);

    egnn_mma_kernel<<<nsm, THREADS, smem_bytes>>>(
        h, x, edist, node_b1, node_b2, coord_b1, coord_w2,
        edge_w1, edge_b1, edge_w2, edge_b2, out);
}

// round 16
// speedup vs baseline: 1.4260x; 1.4260x over previous
#include <cuda_runtime.h>
#include <cstdint>

#define N_NODES 50000
#define N_EDGES 1600000
#define ND 64
#define HD 128
#define ED 32
#define MI 160
#define TILE_E 32
#define NTILES (N_EDGES / TILE_E)
#define THREADS 512
#define FULLMASK 0xffffffffu

#define KT1 20
#define NT1 32
#define KT2 16
#define W1F_WORDS (KT1 * NT1 * 64)   // 40960
#define W2F_WORDS (KT2 * 8 * 64)     // 8192
#define MI_STRIDE 164
#define HID_STRIDE 132
#define MI_WORDS 5248                // 32 * 164

// smem word offsets
#define OFF_W1F   0
#define OFF_MI    40960              // 2 halves x 5248
#define OFF_B1    51456              // 256 (fused node|coord)
#define OFF_B2    51712              // 64
#define OFF_CW2   51776              // 128
#define OFF_EW1   51904              // 32
#define OFF_EB1   51936              // 32
#define OFF_CPART 51968              // 2 x 128
#define OFF_SRC   52224              // 2 x 32
#define OFF_DST   52288              // 2 x 32
#define SMEM_WORDS 52352             // 209,408 bytes

typedef unsigned int u32;

__device__ int g_is64;
__device__ int g_src[N_EDGES];
__device__ int g_dst[N_EDGES];
__device__ u32 g_w1f[W1F_WORDS];
__device__ u32 g_w2f[W2F_WORDS];
__device__ float g_b1f[256];

__global__ void detect_kernel(const unsigned int* __restrict__ w) {
    if (blockIdx.x == 0 && threadIdx.x == 0) {
        int is64 = 1;
        for (int i = 0; i < 64; i++)
            if (w[2 * i + 1] != 0u) { is64 = 0; break; }
        g_is64 = is64;
    }
}

__global__ void convert_kernel(const void* __restrict__ p) {
    int i = blockIdx.x * blockDim.x + threadIdx.x;
    if (i >= N_EDGES) return;
    if (g_is64) {
        const long long* q = (const long long*)p;
        g_src[i] = (int)q[i];
        g_dst[i] = (int)q[N_EDGES + i];
    } else {
        const int* q = (const int*)p;
        g_src[i] = q[i];
        g_dst[i] = q[N_EDGES + i];
    }
}

__global__ void init_out_kernel(const float* __restrict__ h,
                                const float* __restrict__ x,
                                float* __restrict__ out) {
    int i = blockIdx.x * blockDim.x + threadIdx.x;
    const int nh = N_NODES * ND;
    const int total = nh + N_NODES * 3;
    if (i < nh) out[i] = h[i];
    else if (i < total) out[i] = x[i - nh];
}

__device__ __forceinline__ u32 tf32b(float f) {
    u32 u;
    asm("cvt.rna.tf32.f32 %0, %1;" : "=r"(u) : "f"(f));
    return u;
}
// silu(v) = hv + hv*tanh(hv), hv = v/2 : 1 MUFU
__device__ __forceinline__ float silu(float v) {
    float hv = 0.5f * v, t;
    asm("tanh.approx.f32 %0, %1;" : "=f"(t) : "f"(hv));
    return fmaf(hv, t, hv);
}
__device__ __forceinline__ void mma_tf32(
    float& d0, float& d1, float& d2, float& d3,
    u32 a0, u32 a1, u32 a2, u32 a3, u32 b0, u32 b1) {
    asm volatile(
        "mma.sync.aligned.m16n8k8.row.col.f32.tf32.tf32.f32 "
        "{%0,%1,%2,%3}, {%4,%5,%6,%7}, {%8,%9}, {%0,%1,%2,%3};"
        : "+f"(d0), "+f"(d1), "+f"(d2), "+f"(d3)
        : "r"(a0), "r"(a1), "r"(a2), "r"(a3), "r"(b0), "r"(b1));
}
__device__ __forceinline__ void ldsm4(u32& r0, u32& r1, u32& r2, u32& r3, u32 addr) {
    asm volatile("ldmatrix.sync.aligned.m8n8.x4.shared.b16 {%0,%1,%2,%3}, [%4];"
                 : "=r"(r0), "=r"(r1), "=r"(r2), "=r"(r3) : "r"(addr));
}
__device__ __forceinline__ u32 smem_u32(const void* p) {
    return (u32)__cvta_generic_to_shared(p);
}

// W1F rows k>=128 are FUSED with the edge-MLP second layer:
//   W1eff[128+kin][n] = sum_j ew2[kin][j] * W1[128+j][n]   (fp32, then tf32)
__global__ void build_frags(const float* __restrict__ nw1,
                            const float* __restrict__ cw1,
                            const float* __restrict__ nw2,
                            const float* __restrict__ ew2) {
    int i = blockIdx.x * blockDim.x + threadIdx.x;
    if (i < W1F_WORDS) {
        int w = i & 3, lane = (i >> 2) & 31, ntp = (i >> 7) & 15, kt = i >> 11;
        int nt = 2 * ntp + (w >> 1), word = w & 1;
        int n = nt * 8 + (lane >> 2);
        int k = kt * 8 + (lane & 3) + 4 * word;
        float v;
        if (k < 2 * ND) {
            v = (n < HD) ? nw1[k * HD + n] : cw1[k * HD + (n - HD)];
        } else {
            int kin = k - 2 * ND;
            float s = 0.0f;
            for (int jo = 0; jo < ED; jo++) {
                float wv = (n < HD) ? nw1[(2 * ND + jo) * HD + n]
                                    : cw1[(2 * ND + jo) * HD + (n - HD)];
                s = fmaf(ew2[kin * ED + jo], wv, s);
            }
            v = s;
        }
        g_w1f[i] = tf32b(v);
    }
    if (i < W2F_WORDS) {
        int w = i & 3, lane = (i >> 2) & 31, ntp = (i >> 7) & 3, kt = i >> 9;
        int nt = 2 * ntp + (w >> 1), word = w & 1;
        int n = nt * 8 + (lane >> 2);
        int k = kt * 8 + (lane & 3) + 4 * word;
        g_w2f[i] = tf32b(nw2[k * ND + n]);
    }
}

// b1eff[n] = b1[n] + sum_j eb2[j] * W1[128+j][n]   (node | coord concatenated)
__global__ void build_bias(const float* __restrict__ nb1, const float* __restrict__ cb1,
                           const float* __restrict__ eb2,
                           const float* __restrict__ nw1, const float* __restrict__ cw1) {
    int n = threadIdx.x;   // 0..255
    float b = (n < HD) ? nb1[n] : cb1[n - HD];
    for (int jo = 0; jo < ED; jo++) {
        float wv = (n < HD) ? nw1[(2 * ND + jo) * HD + n]
                            : cw1[(2 * ND + jo) * HD + (n - HD)];
        b = fmaf(eb2[jo], wv, b);
    }
    g_b1f[n] = b;
}

// ---------------------------------------------------------------------------
// 512 threads = two independent 8-warp half-pipelines (R13 structure).
// Edge MLP second layer fused into MMA1 weights: MI cols 128..159 hold just
// the elementwise silu(d*ew1+eb1), killing the per-edge shfl/LDS dot loop.
// ---------------------------------------------------------------------------
__global__ void __launch_bounds__(THREADS, 1)
egnn_mma_kernel(const float* __restrict__ h, const float* __restrict__ x,
                const float* __restrict__ edge_dist,
                const float* __restrict__ node_b2, const float* __restrict__ coord_w2,
                const float* __restrict__ edge_w1, const float* __restrict__ edge_b1,
                float* __restrict__ out) {
    extern __shared__ u32 sm[];
    u32* s_w1f = sm + OFF_W1F;
    float* s_b1f  = (float*)(sm + OFF_B1);
    float* s_b2f  = (float*)(sm + OFF_B2);
    float* s_cw2f = (float*)(sm + OFF_CW2);
    float* s_ew1f = (float*)(sm + OFF_EW1);
    float* s_eb1f = (float*)(sm + OFF_EB1);

    const int tid = threadIdx.x;
    const int lane = tid & 31;
    const int warp = tid >> 5;
    const int half = warp >> 3;
    const int hwarp = warp & 7;
    const int htid = tid & 255;

    u32* s_mi = sm + OFF_MI + half * MI_WORDS;
    float* s_cpart = (float*)(sm + OFF_CPART) + half * 128;
    int* s_srci = (int*)(sm + OFF_SRC) + half * 32;
    int* s_dsti = (int*)(sm + OFF_DST) + half * 32;

    {
        const uint4* src1 = (const uint4*)g_w1f;
        uint4* dst1 = (uint4*)s_w1f;
        for (int i = tid; i < W1F_WORDS / 4; i += THREADS) dst1[i] = src1[i];
    }
    if (tid < 256) s_b1f[tid] = g_b1f[tid];
    if (tid < ND) s_b2f[tid] = node_b2[tid];
    if (tid < HD) s_cw2f[tid] = coord_w2[tid];
    if (tid < ED) {
        s_ew1f[tid] = edge_w1[tid];
        s_eb1f[tid] = edge_b1[tid];
    }
    __syncthreads();

    float* out_h = out;
    float* out_x = out + (size_t)N_NODES * ND;

    const int r = lane >> 2;
    const int c = lane & 3;
    const int ge = htid >> 3;     // edge 0..31
    const int gp = htid & 7;      // 16B chunk 0..7
    const int barid = half + 1;

    const u32 lmrow = (lane & 15);
    const u32 lmcol = (lane >> 4) * 4;
    const u32 lm_a_base = smem_u32(s_mi) + ((lmrow * MI_STRIDE + lmcol) << 2);
    const u32 lm_h_base0 = smem_u32(s_mi) + ((lmrow * HID_STRIDE + lmcol) << 2);

#define HBAR() asm volatile("bar.sync %0, 256;" :: "r"(barid) : "memory")

    const int tstride = gridDim.x * 2;
    const int t0 = blockIdx.x * 2 + half;

    // cross-iteration register prefetch: per-thread edge index pair + dist
    int nse = 0, nde = 0;
    float ndist = 0.0f;
    if (t0 < NTILES) {
        nse = g_src[t0 * TILE_E + ge];
        nde = g_dst[t0 * TILE_E + ge];
        ndist = edge_dist[t0 * TILE_E + ge];
    }

    for (int tile = t0; tile < NTILES; tile += tstride) {
        const int se = nse, de = nde;
        const float dcur = ndist;

        // ---- gather h rows (tf32 inline) + indices + elementwise edge pre-act
        {
            if (gp == 0) { s_srci[ge] = se; s_dsti[ge] = de; }
            const uint4* hs = (const uint4*)(h + (size_t)se * ND);
            const uint4* hd = (const uint4*)(h + (size_t)de * ND);
            uint4 v0 = hs[gp], v1 = hs[gp + 8], v2 = hd[gp], v3 = hd[gp + 8];
            uint4* mrow = (uint4*)(s_mi + ge * MI_STRIDE);
            mrow[gp] = make_uint4(tf32b(__uint_as_float(v0.x)), tf32b(__uint_as_float(v0.y)),
                                  tf32b(__uint_as_float(v0.z)), tf32b(__uint_as_float(v0.w)));
            mrow[gp + 8] = make_uint4(tf32b(__uint_as_float(v1.x)), tf32b(__uint_as_float(v1.y)),
                                      tf32b(__uint_as_float(v1.z)), tf32b(__uint_as_float(v1.w)));
            mrow[gp + 16] = make_uint4(tf32b(__uint_as_float(v2.x)), tf32b(__uint_as_float(v2.y)),
                                       tf32b(__uint_as_float(v2.z)), tf32b(__uint_as_float(v2.w)));
            mrow[gp + 24] = make_uint4(tf32b(__uint_as_float(v3.x)), tf32b(__uint_as_float(v3.y)),
                                       tf32b(__uint_as_float(v3.z)), tf32b(__uint_as_float(v3.w)));
            // edge features: cols 128 + 4*gp .. +3 = silu(d*ew1[k]+eb1[k])
            const int k0 = 4 * gp;
            u32 e0v = tf32b(silu(fmaf(dcur, s_ew1f[k0 + 0], s_eb1f[k0 + 0])));
            u32 e1v = tf32b(silu(fmaf(dcur, s_ew1f[k0 + 1], s_eb1f[k0 + 1])));
            u32 e2v = tf32b(silu(fmaf(dcur, s_ew1f[k0 + 2], s_eb1f[k0 + 2])));
            u32 e3v = tf32b(silu(fmaf(dcur, s_ew1f[k0 + 3], s_eb1f[k0 + 3])));
            mrow[32 + gp] = make_uint4(e0v, e1v, e2v, e3v);
        }
        // ---- issue next tile's index/dist loads (retire under MMA1)
        {
            const int ntile = tile + tstride;
            if (ntile < NTILES) {
                nse = g_src[ntile * TILE_E + ge];
                nde = g_dst[ntile * TILE_E + ge];
                ndist = edge_dist[ntile * TILE_E + ge];
            }
        }
        HBAR();

        // ---- hwarp4: x coords (overlaps MMA1)
        float xs0 = 0, xs1 = 0, xs2 = 0, xd0 = 0, xd1 = 0, xd2 = 0;
        if (hwarp == 4) {
            const float* xs = x + (size_t)s_srci[lane] * 3;
            const float* xd = x + (size_t)s_dsti[lane] * 3;
            xs0 = xs[0]; xs1 = xs[1]; xs2 = xs[2];
            xd0 = xd[0]; xd1 = xd[1]; xd2 = xd[2];
        }

        // ---- MMA1: [32,160] x [160,256]
        float acc[2][4][4];
#pragma unroll
        for (int mt = 0; mt < 2; mt++)
#pragma unroll
            for (int nt = 0; nt < 4; nt++)
#pragma unroll
                for (int q = 0; q < 4; q++) acc[mt][nt][q] = 0.0f;

#pragma unroll 4
        for (int kt = 0; kt < KT1; kt++) {
            u32 a[2][4];
            ldsm4(a[0][0], a[0][1], a[0][2], a[0][3], lm_a_base + (kt * 8 << 2));
            ldsm4(a[1][0], a[1][1], a[1][2], a[1][3],
                  lm_a_base + ((16 * MI_STRIDE + kt * 8) << 2));
#pragma unroll
            for (int p = 0; p < 2; p++) {
                uint4 bv = *(const uint4*)&s_w1f[((kt * 16 + hwarp * 2 + p) * 32 + lane) * 4];
#pragma unroll
                for (int mt = 0; mt < 2; mt++) {
                    mma_tf32(acc[mt][2 * p][0], acc[mt][2 * p][1],
                             acc[mt][2 * p][2], acc[mt][2 * p][3],
                             a[mt][0], a[mt][1], a[mt][2], a[mt][3], bv.x, bv.y);
                    mma_tf32(acc[mt][2 * p + 1][0], acc[mt][2 * p + 1][1],
                             acc[mt][2 * p + 1][2], acc[mt][2 * p + 1][3],
                             a[mt][0], a[mt][1], a[mt][2], a[mt][3], bv.z, bv.w);
                }
            }
        }

        // ---- coord warps: silu + weighted reduce -> cpart
        if (hwarp >= 4) {
            const int cw0 = (hwarp - 4) * 32;
#pragma unroll
            for (int mt = 0; mt < 2; mt++) {
                float pr = 0.0f, pr8 = 0.0f;
#pragma unroll
                for (int nt = 0; nt < 4; nt++) {
                    const int cc = cw0 + nt * 8 + 2 * c;
                    float b1a = s_b1f[HD + cc], b1b = s_b1f[HD + cc + 1];
                    float w2a = s_cw2f[cc], w2b = s_cw2f[cc + 1];
                    pr  = fmaf(silu(acc[mt][nt][0] + b1a), w2a, pr);
                    pr  = fmaf(silu(acc[mt][nt][1] + b1b), w2b, pr);
                    pr8 = fmaf(silu(acc[mt][nt][2] + b1a), w2a, pr8);
                    pr8 = fmaf(silu(acc[mt][nt][3] + b1b), w2b, pr8);
                }
                pr  += __shfl_xor_sync(FULLMASK, pr, 1);
                pr  += __shfl_xor_sync(FULLMASK, pr, 2);
                pr8 += __shfl_xor_sync(FULLMASK, pr8, 1);
                pr8 += __shfl_xor_sync(FULLMASK, pr8, 2);
                if (c == 0) {
                    s_cpart[(hwarp - 4) * 32 + mt * 16 + r] = pr;
                    s_cpart[(hwarp - 4) * 32 + mt * 16 + r + 8] = pr8;
                }
            }
        }
        HBAR();

        // ---- node warps: silu'd hidden (tf32) -> s_mi; hwarp4: x scatter
        if (hwarp < 4) {
#pragma unroll
            for (int mt = 0; mt < 2; mt++)
#pragma unroll
                for (int nt = 0; nt < 4; nt++) {
                    const int col = hwarp * 32 + nt * 8 + 2 * c;
                    float b1a = s_b1f[col], b1b = s_b1f[col + 1];
                    u32 v0 = tf32b(silu(acc[mt][nt][0] + b1a));
                    u32 v1 = tf32b(silu(acc[mt][nt][1] + b1b));
                    u32 v2 = tf32b(silu(acc[mt][nt][2] + b1a));
                    u32 v3 = tf32b(silu(acc[mt][nt][3] + b1b));
                    u32* row0 = s_mi + (mt * 16 + r) * HID_STRIDE + col;
                    u32* row8 = row0 + 8 * HID_STRIDE;
                    *(uint2*)row0 = make_uint2(v0, v1);
                    *(uint2*)row8 = make_uint2(v2, v3);
                }
        } else if (hwarp == 4) {
            float cwv = s_cpart[lane] + s_cpart[32 + lane] +
                        s_cpart[64 + lane] + s_cpart[96 + lane];
            float dx = xs0 - xd0, dy = xs1 - xd1, dz = xs2 - xd2;
            float len = fmaxf(sqrtf(dx * dx + dy * dy + dz * dz), 1e-8f);
            float s = __fdividef(cwv, len);
            float* dstx = out_x + (size_t)s_dsti[lane] * 3;
            atomicAdd(dstx + 0, s * dx);
            atomicAdd(dstx + 1, s * dy);
            atomicAdd(dstx + 2, s * dz);
        }
        HBAR();

        // ---- MMA2: [32,128] x [128,64]  (B quads streamed from L2)
        {
            const int mt2 = hwarp >> 2;
            const int nc = hwarp & 3;
            const u32 lm_h = lm_h_base0 + ((mt2 * 16 * HID_STRIDE) << 2);
            float a2[2][4];
#pragma unroll
            for (int nt = 0; nt < 2; nt++)
#pragma unroll
                for (int q = 0; q < 4; q++) a2[nt][q] = 0.0f;

#pragma unroll 4
            for (int kt = 0; kt < KT2; kt++) {
                u32 a0, a1, av2, a3;
                ldsm4(a0, a1, av2, a3, lm_h + (kt * 8 << 2));
                uint4 bv = __ldg((const uint4*)g_w2f + (kt * 4 + nc) * 32 + lane);
                mma_tf32(a2[0][0], a2[0][1], a2[0][2], a2[0][3],
                         a0, a1, av2, a3, bv.x, bv.y);
                mma_tf32(a2[1][0], a2[1][1], a2[1][2], a2[1][3],
                         a0, a1, av2, a3, bv.z, bv.w);
            }
#pragma unroll
            for (int nt = 0; nt < 2; nt++) {
                const int col = nc * 16 + nt * 8 + 2 * c;
                float b2a = s_b2f[col], b2b = s_b2f[col + 1];
                int eA = mt2 * 16 + r;
                float* baseA = out_h + (size_t)s_dsti[eA] * ND + col;
                atomicAdd((float2*)baseA, make_float2(a2[nt][0] + b2a, a2[nt][1] + b2b));
                float* baseB = out_h + (size_t)s_dsti[eA + 8] * ND + col;
                atomicAdd((float2*)baseB, make_float2(a2[nt][2] + b2a, a2[nt][3] + b2b));
            }
        }
        HBAR();
    }
#undef HBAR
}

extern "C" void kernel_launch(void* const* d_in, const int* in_sizes, int n_in,
                              void* d_out, int out_size) {
    const float* h        = (const float*)d_in[0];
    const float* x        = (const float*)d_in[1];
    const void*  eidx     = d_in[2];
    const float* edist    = (const float*)d_in[3];
    const float* node_w1  = (const float*)d_in[4];
    const float* node_b1  = (const float*)d_in[5];
    const float* node_w2  = (const float*)d_in[6];
    const float* node_b2  = (const float*)d_in[7];
    const float* coord_w1 = (const float*)d_in[8];
    const float* coord_b1 = (const float*)d_in[9];
    const float* coord_w2 = (const float*)d_in[10];
    const float* edge_w1  = (const float*)d_in[11];
    const float* edge_b1  = (const float*)d_in[12];
    const float* edge_w2  = (const float*)d_in[13];
    const float* edge_b2  = (const float*)d_in[14];
    float* out = (float*)d_out;

    (void)in_sizes; (void)n_in; (void)out_size;

    detect_kernel<<<1, 32>>>((const unsigned int*)eidx);
    convert_kernel<<<(N_EDGES + 255) / 256, 256>>>(eidx);
    build_frags<<<(W1F_WORDS + 255) / 256, 256>>>(node_w1, coord_w1, node_w2, edge_w2);
    build_bias<<<1, 256>>>(node_b1, coord_b1, edge_b2, node_w1, coord_w1);

    const int total_out = N_NODES * ND + N_NODES * 3;
    init_out_kernel<<<(total_out + 255) / 256, 256>>>(h, x, out);

    const int smem_bytes = SMEM_WORDS * 4;
    cudaFuncSetAttribute(egnn_mma_kernel,
                         cudaFuncAttributeMaxDynamicSharedMemorySize, smem_bytes);

    int nsm = 148;
    cudaDeviceGetAttribute(&nsm, cudaDevAttrMultiProcessorCount, 0);

    egnn_mma_kernel<<<nsm, THREADS, smem_bytes>>>(
        h, x, edist, node_b2, coord_w2, edge_w1, edge_b1, out);
}